// round 2
// baseline (speedup 1.0000x reference)
#include <cuda_runtime.h>
#include <math.h>
#include <float.h>

// ---------------- problem constants ----------------
#define B_DIM   2
#define S_LEN   2048
#define C_DIM   2048
#define HD      64
#define NH      (C_DIM / HD)          // 32 heads
#define M_TOT   (B_DIM * S_LEN)       // 4096 rows
#define QKV_N   (3 * C_DIM)           // 6144

// ---------------- scratch (device globals; no allocs allowed) ----------------
__device__ float g_qkv[(size_t)M_TOT * QKV_N];               // [B*S, 3C]   96 MB
__device__ float g_q  [(size_t)B_DIM * NH * S_LEN * HD];     // [B,H,S,hd]  32 MB
__device__ float g_k  [(size_t)B_DIM * NH * S_LEN * HD];
__device__ float g_v  [(size_t)B_DIM * NH * S_LEN * HD];
__device__ float g_att[(size_t)M_TOT * C_DIM];               // [B,S,C]     32 MB

// ============================================================================
// SGEMM NT:  C[m,n] = sum_k A[m,k] * B[n,k]
// A: MxK row-major, B: NxK row-major, C: MxN row-major.
// 128x128 block tile, BK=16, 256 threads, 8x8 microtile, double-buffered smem.
// ============================================================================
#define GBM 128
#define GBN 128
#define GBK 16

__global__ void __launch_bounds__(256) sgemm_nt(
    const float* __restrict__ A, const float* __restrict__ B,
    float* __restrict__ C, int M, int N, int K)
{
    __shared__ float As[2][GBK][GBM + 4];
    __shared__ float Bs[2][GBK][GBN + 4];

    const int tx = threadIdx.x, ty = threadIdx.y;
    const int tid = ty * 16 + tx;
    const int m0 = blockIdx.y * GBM;
    const int n0 = blockIdx.x * GBN;

    // each thread loads 2 float4 from A and 2 from B per tile
    const int r0 = tid >> 2;                  // 0..63  (row pairs: r0, r0+64)
    const int k4 = (tid & 3) << 2;            // 0,4,8,12

    float acc[8][8];
    #pragma unroll
    for (int i = 0; i < 8; i++)
        #pragma unroll
        for (int j = 0; j < 8; j++) acc[i][j] = 0.f;

    // ---- preload tile 0 into buffer 0 ----
    {
        #pragma unroll
        for (int l = 0; l < 2; l++) {
            int r = r0 + l * 64;
            float4 va = *(const float4*)&A[(size_t)(m0 + r) * K + k4];
            As[0][k4 + 0][r] = va.x; As[0][k4 + 1][r] = va.y;
            As[0][k4 + 2][r] = va.z; As[0][k4 + 3][r] = va.w;
            float4 vb = *(const float4*)&B[(size_t)(n0 + r) * K + k4];
            Bs[0][k4 + 0][r] = vb.x; Bs[0][k4 + 1][r] = vb.y;
            Bs[0][k4 + 2][r] = vb.z; Bs[0][k4 + 3][r] = vb.w;
        }
    }
    __syncthreads();

    int p = 0;
    for (int kt = 0; kt < K; kt += GBK) {
        // ---- issue next tile's gmem loads into buffer p^1 ----
        if (kt + GBK < K) {
            #pragma unroll
            for (int l = 0; l < 2; l++) {
                int r = r0 + l * 64;
                float4 va = *(const float4*)&A[(size_t)(m0 + r) * K + kt + GBK + k4];
                As[p ^ 1][k4 + 0][r] = va.x; As[p ^ 1][k4 + 1][r] = va.y;
                As[p ^ 1][k4 + 2][r] = va.z; As[p ^ 1][k4 + 3][r] = va.w;
                float4 vb = *(const float4*)&B[(size_t)(n0 + r) * K + kt + GBK + k4];
                Bs[p ^ 1][k4 + 0][r] = vb.x; Bs[p ^ 1][k4 + 1][r] = vb.y;
                Bs[p ^ 1][k4 + 2][r] = vb.z; Bs[p ^ 1][k4 + 3][r] = vb.w;
            }
        }

        // ---- compute on buffer p ----
        #pragma unroll
        for (int kk = 0; kk < GBK; kk++) {
            float a[8], b[8];
            *(float4*)&a[0] = *(const float4*)&As[p][kk][ty * 8];
            *(float4*)&a[4] = *(const float4*)&As[p][kk][ty * 8 + 4];
            *(float4*)&b[0] = *(const float4*)&Bs[p][kk][tx * 8];
            *(float4*)&b[4] = *(const float4*)&Bs[p][kk][tx * 8 + 4];
            #pragma unroll
            for (int i = 0; i < 8; i++)
                #pragma unroll
                for (int j = 0; j < 8; j++)
                    acc[i][j] += a[i] * b[j];
        }
        __syncthreads();
        p ^= 1;
    }

    #pragma unroll
    for (int i = 0; i < 8; i++) {
        float* cp = &C[(size_t)(m0 + ty * 8 + i) * N + n0 + tx * 8];
        *(float4*)cp       = make_float4(acc[i][0], acc[i][1], acc[i][2], acc[i][3]);
        *(float4*)(cp + 4) = make_float4(acc[i][4], acc[i][5], acc[i][6], acc[i][7]);
    }
}

// ============================================================================
// Fused per-head LayerNorm + rotary + layout transpose.
// One warp handles one (b, s, h) head: 64 values -> 2 per lane.
// Q gets the 1/sqrt(hd) score scale folded in.
// Output layout: [B, H, S, hd] for coalesced attention tiles.
// ============================================================================
__device__ __forceinline__ float2 ln_pair(float a, float b,
                                          const float* __restrict__ g,
                                          const float* __restrict__ be, int d0)
{
    float s = a + b;
    #pragma unroll
    for (int off = 16; off; off >>= 1) s += __shfl_xor_sync(0xffffffffu, s, off);
    float mean = s * 0.015625f;               // /64
    float da = a - mean, db = b - mean;
    float v = da * da + db * db;
    #pragma unroll
    for (int off = 16; off; off >>= 1) v += __shfl_xor_sync(0xffffffffu, v, off);
    float rstd = rsqrtf(v * 0.015625f + 1e-5f);
    return make_float2(da * rstd * g[d0] + be[d0],
                       db * rstd * g[d0 + 1] + be[d0 + 1]);
}

__global__ void __launch_bounds__(256) ln_rope_kernel(
    const float* __restrict__ qkv, const float* __restrict__ rope,
    const float* __restrict__ qg, const float* __restrict__ qb,
    const float* __restrict__ kg, const float* __restrict__ kb,
    float* __restrict__ Q, float* __restrict__ Ko, float* __restrict__ V)
{
    const int warp = threadIdx.x >> 5;
    const int lane = threadIdx.x & 31;
    const long task = (long)blockIdx.x * 8 + warp;       // b*S*NH tasks
    const int h = (int)(task % NH);
    const int s = (int)((task / NH) % S_LEN);
    const int b = (int)(task / ((long)NH * S_LEN));

    const size_t base = ((size_t)b * S_LEN + s) * QKV_N + h * (3 * HD);
    const int d0 = lane * 2;

    float2 qv = *(const float2*)&qkv[base + d0];
    float2 kv = *(const float2*)&qkv[base + HD + d0];
    float2 vv = *(const float2*)&qkv[base + 2 * HD + d0];

    float2 qn = ln_pair(qv.x, qv.y, qg, qb, d0);
    float2 kn = ln_pair(kv.x, kv.y, kg, kb, d0);

    // rope[s, 0, i=lane, j, l] flat: s*128 + lane*4 + j*2 + l
    float4 rr = *(const float4*)&rope[(size_t)s * 128 + lane * 4];
    float q0 = rr.x * qn.x + rr.y * qn.y;     // j=0
    float q1 = rr.z * qn.x + rr.w * qn.y;     // j=1
    float k0 = rr.x * kn.x + rr.y * kn.y;
    float k1 = rr.z * kn.x + rr.w * kn.y;

    const size_t ob = (((size_t)b * NH + h) * S_LEN + s) * HD + d0;
    *(float2*)&Q[ob]  = make_float2(q0 * 0.125f, q1 * 0.125f);  // fold 1/sqrt(64)
    *(float2*)&Ko[ob] = make_float2(k0, k1);
    *(float2*)&V[ob]  = vv;
}

// ============================================================================
// Flash attention, fp32. Grid: (S/64 q-tiles, B*NH). Block 16x16.
// Tiles Br=Bc=64, hd=64. Q/K stored transposed [d][r] in smem for float4 LDS;
// V natural [c][d]; P staged [c][r] for the PV product.
// K/V gmem loads are issued into registers BEFORE the barrier protecting the
// smem overwrite, hiding load latency behind the barrier wait.
// ============================================================================
#define AST 68                         // smem row stride (floats)
#define ATT_SMEM (4 * 64 * AST * 4)    // 69632 bytes

__global__ void __launch_bounds__(256) attn_kernel(
    const float* __restrict__ Qg, const float* __restrict__ Kg,
    const float* __restrict__ Vg, float* __restrict__ Og)
{
    extern __shared__ float sm[];
    float* Qs = sm;                    // [d][r]
    float* Ks = sm + 64 * AST;         // [d][c]
    float* Vs = sm + 2 * 64 * AST;     // [c][d]
    float* Ps = sm + 3 * 64 * AST;     // [c][r]

    const int tx = threadIdx.x, ty = threadIdx.y;
    const int tid = ty * 16 + tx;
    const int bh = blockIdx.y;
    const int q0 = blockIdx.x * 64;
    const size_t qbase = ((size_t)bh * S_LEN + q0) * HD;

    // per-thread K/V load coordinates (4 chunks of 256 threads cover 64x64)
    int lr[4], ld[4];
    #pragma unroll
    for (int l = 0; l < 4; l++) {
        int idx = tid + l * 256;       // 0..1023
        lr[l] = idx >> 4;              // 0..63
        ld[l] = (idx & 15) << 2;       // 0..60
    }

    // load Q tile transposed
    #pragma unroll
    for (int l = 0; l < 4; l++) {
        float4 v = *(const float4*)&Qg[qbase + (size_t)lr[l] * HD + ld[l]];
        Qs[(ld[l] + 0) * AST + lr[l]] = v.x;
        Qs[(ld[l] + 1) * AST + lr[l]] = v.y;
        Qs[(ld[l] + 2) * AST + lr[l]] = v.z;
        Qs[(ld[l] + 3) * AST + lr[l]] = v.w;
    }

    float m_[4], l_[4], o_[4][4];
    #pragma unroll
    for (int i = 0; i < 4; i++) {
        m_[i] = -FLT_MAX; l_[i] = 0.f;
        #pragma unroll
        for (int j = 0; j < 4; j++) o_[i][j] = 0.f;
    }

    for (int jt = 0; jt < S_LEN / 64; jt++) {
        const size_t kb = ((size_t)bh * S_LEN + jt * 64) * HD;

        // prefetch K/V into registers before the barrier
        float4 kreg[4], vreg[4];
        #pragma unroll
        for (int l = 0; l < 4; l++) {
            kreg[l] = *(const float4*)&Kg[kb + (size_t)lr[l] * HD + ld[l]];
            vreg[l] = *(const float4*)&Vg[kb + (size_t)lr[l] * HD + ld[l]];
        }

        __syncthreads();               // prior iter's Ps/Vs reads done
        #pragma unroll
        for (int l = 0; l < 4; l++) {
            Ks[(ld[l] + 0) * AST + lr[l]] = kreg[l].x;
            Ks[(ld[l] + 1) * AST + lr[l]] = kreg[l].y;
            Ks[(ld[l] + 2) * AST + lr[l]] = kreg[l].z;
            Ks[(ld[l] + 3) * AST + lr[l]] = kreg[l].w;
            *(float4*)&Vs[lr[l] * AST + ld[l]] = vreg[l];
        }
        __syncthreads();

        // S = Q K^T (scale already folded into Q)
        float sreg[4][4];
        #pragma unroll
        for (int i = 0; i < 4; i++)
            #pragma unroll
            for (int j = 0; j < 4; j++) sreg[i][j] = 0.f;

        #pragma unroll 8
        for (int d = 0; d < 64; d++) {
            float qa[4], ka[4];
            *(float4*)qa = *(const float4*)&Qs[d * AST + ty * 4];
            *(float4*)ka = *(const float4*)&Ks[d * AST + tx * 4];
            #pragma unroll
            for (int i = 0; i < 4; i++)
                #pragma unroll
                for (int j = 0; j < 4; j++)
                    sreg[i][j] += qa[i] * ka[j];
        }

        // online softmax update (lanes 0-15 / 16-31 share a ty -> xor<=8 ok)
        #pragma unroll
        for (int i = 0; i < 4; i++) {
            float mx = fmaxf(fmaxf(sreg[i][0], sreg[i][1]),
                             fmaxf(sreg[i][2], sreg[i][3]));
            #pragma unroll
            for (int off = 8; off; off >>= 1)
                mx = fmaxf(mx, __shfl_xor_sync(0xffffffffu, mx, off));
            float mn = fmaxf(m_[i], mx);
            float alpha = __expf(m_[i] - mn);
            m_[i] = mn;
            float rs = 0.f;
            #pragma unroll
            for (int j = 0; j < 4; j++) {
                float p = __expf(sreg[i][j] - mn);
                sreg[i][j] = p;
                rs += p;
            }
            #pragma unroll
            for (int off = 8; off; off >>= 1)
                rs += __shfl_xor_sync(0xffffffffu, rs, off);
            l_[i] = l_[i] * alpha + rs;
            #pragma unroll
            for (int j = 0; j < 4; j++) o_[i][j] *= alpha;
        }

        // stage P in smem as [c][r]
        #pragma unroll
        for (int j = 0; j < 4; j++)
            #pragma unroll
            for (int i = 0; i < 4; i++)
                Ps[(tx * 4 + j) * AST + ty * 4 + i] = sreg[i][j];
        __syncthreads();

        // O += P V
        #pragma unroll 8
        for (int c = 0; c < 64; c++) {
            float pa[4], va[4];
            *(float4*)pa = *(const float4*)&Ps[c * AST + ty * 4];
            *(float4*)va = *(const float4*)&Vs[c * AST + tx * 4];
            #pragma unroll
            for (int i = 0; i < 4; i++)
                #pragma unroll
                for (int j = 0; j < 4; j++)
                    o_[i][j] += pa[i] * va[j];
        }
    }

    // epilogue: normalize and scatter back to [B, S, C]
    const int b = bh >> 5;      // / NH
    const int h = bh & 31;      // % NH
    #pragma unroll
    for (int i = 0; i < 4; i++) {
        float inv = 1.f / l_[i];
        int row = q0 + ty * 4 + i;
        float4 v = make_float4(o_[i][0] * inv, o_[i][1] * inv,
                               o_[i][2] * inv, o_[i][3] * inv);
        *(float4*)&Og[((size_t)b * S_LEN + row) * C_DIM + h * HD + tx * 4] = v;
    }
}

// ============================================================================
// launch
// ============================================================================
extern "C" void kernel_launch(void* const* d_in, const int* in_sizes, int n_in,
                              void* d_out, int out_size)
{
    const float* x    = (const float*)d_in[0];
    const float* rope = (const float*)d_in[1];
    const float* wqkv = (const float*)d_in[2];
    const float* wout = (const float*)d_in[3];
    const float* qg   = (const float*)d_in[4];
    const float* qb   = (const float*)d_in[5];
    const float* kg   = (const float*)d_in[6];
    const float* kb   = (const float*)d_in[7];
    float* out = (float*)d_out;

    float *qkv, *Q, *K, *V, *att;
    cudaGetSymbolAddress((void**)&qkv, g_qkv);
    cudaGetSymbolAddress((void**)&Q,   g_q);
    cudaGetSymbolAddress((void**)&K,   g_k);
    cudaGetSymbolAddress((void**)&V,   g_v);
    cudaGetSymbolAddress((void**)&att, g_att);

    cudaFuncSetAttribute(attn_kernel,
                         cudaFuncAttributeMaxDynamicSharedMemorySize, ATT_SMEM);

    dim3 blk(16, 16);

    // 1) QKV projection: [4096,2048] x [6144,2048]^T -> [4096,6144]
    sgemm_nt<<<dim3(QKV_N / GBN, M_TOT / GBM), blk>>>(x, wqkv, qkv,
                                                      M_TOT, QKV_N, C_DIM);
    // 2) LN + rope + transpose to [B,H,S,hd]
    ln_rope_kernel<<<(B_DIM * S_LEN * NH) / 8, 256>>>(qkv, rope,
                                                      qg, qb, kg, kb, Q, K, V);
    // 3) flash attention -> [B,S,C]
    attn_kernel<<<dim3(S_LEN / 64, B_DIM * NH), blk, ATT_SMEM>>>(Q, K, V, att);
    // 4) output projection: [4096,2048] x [2048,2048]^T -> d_out
    sgemm_nt<<<dim3(C_DIM / GBN, M_TOT / GBM), blk>>>(att, wout, out,
                                                      M_TOT, C_DIM, C_DIM);
}

// round 12
// speedup vs baseline: 1.6509x; 1.6509x over previous
#include <cuda_runtime.h>
#include <cuda_bf16.h>
#include <math.h>
#include <float.h>
#include <stdint.h>

// ---------------- problem constants ----------------
#define B_DIM   2
#define S_LEN   2048
#define C_DIM   2048
#define HD      64
#define NH      (C_DIM / HD)          // 32 heads
#define M_TOT   (B_DIM * S_LEN)       // 4096 rows
#define QKV_N   (3 * C_DIM)           // 6144

// ---------------- scratch (device globals; no allocs allowed) ----------------
__device__ float g_qkv[(size_t)M_TOT * QKV_N];               // [B*S, 3C]
__device__ float g_q  [(size_t)B_DIM * NH * S_LEN * HD];     // [B,H,S,hd]
__device__ float g_k  [(size_t)B_DIM * NH * S_LEN * HD];
__device__ float g_v  [(size_t)B_DIM * NH * S_LEN * HD];

// bf16 hi/lo decompositions for tensor-core GEMMs
__device__ __align__(16) __nv_bfloat16 g_xh [(size_t)M_TOT * C_DIM];
__device__ __align__(16) __nv_bfloat16 g_xl [(size_t)M_TOT * C_DIM];
__device__ __align__(16) __nv_bfloat16 g_wqh[(size_t)QKV_N * C_DIM];
__device__ __align__(16) __nv_bfloat16 g_wql[(size_t)QKV_N * C_DIM];
__device__ __align__(16) __nv_bfloat16 g_woh[(size_t)C_DIM * C_DIM];
__device__ __align__(16) __nv_bfloat16 g_wol[(size_t)C_DIM * C_DIM];
__device__ __align__(16) __nv_bfloat16 g_ah [(size_t)M_TOT * C_DIM];
__device__ __align__(16) __nv_bfloat16 g_al [(size_t)M_TOT * C_DIM];

// ============================================================================
// helpers: cp.async, ldmatrix, mma.sync (all valid on base sm_103 target)
// ============================================================================
#define SMEM_SWIZZLE_128B(off) ((off) ^ (((off) >> 3) & 0x70))

__device__ __forceinline__ void cp16(uint32_t s, const void* g) {
    uint64_t ga = (uint64_t)__cvta_generic_to_global(g);
    asm volatile("cp.async.cg.shared.global [%0], [%1], 16;" :: "r"(s), "l"(ga));
}
__device__ __forceinline__ void cp_commit() { asm volatile("cp.async.commit_group;" ::: "memory"); }
template<int N> __device__ __forceinline__ void cp_wait() {
    asm volatile("cp.async.wait_group %0;" :: "n"(N) : "memory");
}

__device__ __forceinline__ void ldsm_x4(uint32_t* r, uint32_t addr) {
    asm volatile("ldmatrix.sync.aligned.m8n8.x4.shared.b16 {%0,%1,%2,%3}, [%4];"
                 : "=r"(r[0]), "=r"(r[1]), "=r"(r[2]), "=r"(r[3]) : "r"(addr));
}
// D += A(m16k16 bf16, row) * B(k16n8 bf16, col), fp32 accum
__device__ __forceinline__ void mma_bf16(float* c, const uint32_t* a,
                                         uint32_t b0, uint32_t b1) {
    asm volatile(
        "mma.sync.aligned.m16n8k16.row.col.f32.bf16.bf16.f32 "
        "{%0,%1,%2,%3}, {%4,%5,%6,%7}, {%8,%9}, {%0,%1,%2,%3};"
        : "+f"(c[0]), "+f"(c[1]), "+f"(c[2]), "+f"(c[3])
        : "r"(a[0]), "r"(a[1]), "r"(a[2]), "r"(a[3]), "r"(b0), "r"(b1));
}

// ============================================================================
// fp32 -> (bf16 hi, bf16 lo) split. 8 elems per thread.
// ============================================================================
__global__ void __launch_bounds__(256) cvt_hilo(
    const float* __restrict__ in, __nv_bfloat16* __restrict__ hi,
    __nv_bfloat16* __restrict__ lo)
{
    size_t i = (size_t)blockIdx.x * blockDim.x + threadIdx.x;
    const float4* p = (const float4*)in + i * 2;
    float4 a = p[0], b = p[1];
    float v[8] = {a.x, a.y, a.z, a.w, b.x, b.y, b.z, b.w};
    __nv_bfloat16 h[8], l[8];
    #pragma unroll
    for (int j = 0; j < 8; j++) {
        h[j] = __float2bfloat16(v[j]);
        l[j] = __float2bfloat16(v[j] - __bfloat162float(h[j]));
    }
    *((uint4*)hi + i) = *(const uint4*)h;
    *((uint4*)lo + i) = *(const uint4*)l;
}

// ============================================================================
// mma.sync bf16x2 GEMM NT: C[m,n] = sum_k A[m,k]*B[n,k]  (near-fp32 accurate)
// 3 HMMA terms per product: AhBh + AhBl + AlBh.
// Tile 128x128, BK=64 bf16 (128B SW128 rows). 256 threads = 8 warps,
// warp grid 4(m)x2(n), warp tile 32x64. cp.async double-buffered.
// ============================================================================
#define TBM 128
#define TBN 128
#define TBK 64
#define OFF_AH 0
#define OFF_AL 16384
#define OFF_BH 32768
#define OFF_BL 49152
#define STAGE  65536
#define GEMM_SMEM (2 * STAGE)          // 131072 B

__device__ __forceinline__ void load_tile_mma(
    const __nv_bfloat16* __restrict__ Ah, const __nv_bfloat16* __restrict__ Al,
    const __nv_bfloat16* __restrict__ Bh, const __nv_bfloat16* __restrict__ Bl,
    uint32_t sb, int m0, int n0, int K, int kt, int buf, int tid)
{
    const size_t koff = (size_t)kt * TBK;
    const uint32_t st = sb + buf * STAGE;
    #pragma unroll
    for (int t = 0; t < 4; t++) {
        int idx = tid + t * 256;             // 0..1023: 128 rows x 8 16B units
        int r = idx >> 3, u = idx & 7;
        uint32_t so = SMEM_SWIZZLE_128B((uint32_t)(r * 128 + u * 16));
        size_t goA = (size_t)(m0 + r) * K + koff + u * 8;
        size_t goB = (size_t)(n0 + r) * K + koff + u * 8;
        cp16(st + OFF_AH + so, Ah + goA);
        cp16(st + OFF_AL + so, Al + goA);
        cp16(st + OFF_BH + so, Bh + goB);
        cp16(st + OFF_BL + so, Bl + goB);
    }
    cp_commit();
}

__global__ void __launch_bounds__(256) gemm_mma(
    const __nv_bfloat16* __restrict__ Ah, const __nv_bfloat16* __restrict__ Al,
    const __nv_bfloat16* __restrict__ Bh, const __nv_bfloat16* __restrict__ Bl,
    float* __restrict__ C, int M, int N, int K)
{
    extern __shared__ char gsm[];
    const uint32_t sb = (uint32_t)__cvta_generic_to_shared(gsm);
    const int tid  = threadIdx.x;
    const int wid  = tid >> 5;
    const int lane = tid & 31;
    const int wm   = wid & 3;            // m block: rows wm*32
    const int wn   = wid >> 2;           // n block: cols wn*64
    const int m0 = blockIdx.y * TBM;
    const int n0 = blockIdx.x * TBN;

    float acc[2][8][4];
    #pragma unroll
    for (int i = 0; i < 2; i++)
        #pragma unroll
        for (int j = 0; j < 8; j++)
            #pragma unroll
            for (int c = 0; c < 4; c++) acc[i][j][c] = 0.f;

    load_tile_mma(Ah, Al, Bh, Bl, sb, m0, n0, K, 0, 0, tid);

    const int NK = K / TBK;
    const int lrow = lane & 15;          // ldmatrix row within 16
    const int lu   = lane >> 4;          // ldmatrix 16B-unit select

    for (int kt = 0; kt < NK; kt++) {
        if (kt + 1 < NK) {
            load_tile_mma(Ah, Al, Bh, Bl, sb, m0, n0, K, kt + 1, (kt + 1) & 1, tid);
            cp_wait<1>();
        } else {
            cp_wait<0>();
        }
        __syncthreads();

        const uint32_t st = sb + (kt & 1) * STAGE;
        #pragma unroll
        for (int kc = 0; kc < 4; kc++) {
            const int u = 2 * kc + lu;
            // A fragments (2 m16 tiles), hi and lo
            uint32_t afh[2][4], afl[2][4];
            #pragma unroll
            for (int mi = 0; mi < 2; mi++) {
                int r = wm * 32 + mi * 16 + lrow;
                uint32_t so = SMEM_SWIZZLE_128B((uint32_t)(r * 128 + u * 16));
                ldsm_x4(afh[mi], st + OFF_AH + so);
                ldsm_x4(afl[mi], st + OFF_AL + so);
            }
            // B fragment groups: each x4 covers n16 -> 2 n8 frags
            #pragma unroll
            for (int bg = 0; bg < 4; bg++) {
                int rn = wn * 64 + bg * 16 + lrow;
                uint32_t so = SMEM_SWIZZLE_128B((uint32_t)(rn * 128 + u * 16));
                uint32_t bfh[4], bfl[4];
                ldsm_x4(bfh, st + OFF_BH + so);
                ldsm_x4(bfl, st + OFF_BL + so);
                #pragma unroll
                for (int mi = 0; mi < 2; mi++) {
                    // n8 frag 0 of this group: regs {r0, r2}
                    mma_bf16(acc[mi][2 * bg + 0], afh[mi], bfh[0], bfh[2]);
                    mma_bf16(acc[mi][2 * bg + 0], afh[mi], bfl[0], bfl[2]);
                    mma_bf16(acc[mi][2 * bg + 0], afl[mi], bfh[0], bfh[2]);
                    // n8 frag 1: regs {r1, r3}
                    mma_bf16(acc[mi][2 * bg + 1], afh[mi], bfh[1], bfh[3]);
                    mma_bf16(acc[mi][2 * bg + 1], afh[mi], bfl[1], bfl[3]);
                    mma_bf16(acc[mi][2 * bg + 1], afl[mi], bfh[1], bfh[3]);
                }
            }
        }
        __syncthreads();
    }

    // epilogue: frag layout -> C
    const int row0 = m0 + wm * 32 + (lane >> 2);
    const int col0 = n0 + wn * 64 + (lane & 3) * 2;
    #pragma unroll
    for (int mi = 0; mi < 2; mi++) {
        #pragma unroll
        for (int nj = 0; nj < 8; nj++) {
            size_t base = (size_t)(row0 + mi * 16) * N + col0 + nj * 8;
            *(float2*)&C[base]                = make_float2(acc[mi][nj][0], acc[mi][nj][1]);
            *(float2*)&C[base + (size_t)8 * N] = make_float2(acc[mi][nj][2], acc[mi][nj][3]);
        }
    }
}

// ============================================================================
// Fused per-head LayerNorm + rotary + layout transpose (unchanged).
// ============================================================================
__device__ __forceinline__ float2 ln_pair(float a, float b,
                                          const float* __restrict__ g,
                                          const float* __restrict__ be, int d0)
{
    float s = a + b;
    #pragma unroll
    for (int off = 16; off; off >>= 1) s += __shfl_xor_sync(0xffffffffu, s, off);
    float mean = s * 0.015625f;
    float da = a - mean, db = b - mean;
    float v = da * da + db * db;
    #pragma unroll
    for (int off = 16; off; off >>= 1) v += __shfl_xor_sync(0xffffffffu, v, off);
    float rstd = rsqrtf(v * 0.015625f + 1e-5f);
    return make_float2(da * rstd * g[d0] + be[d0],
                       db * rstd * g[d0 + 1] + be[d0 + 1]);
}

__global__ void __launch_bounds__(256) ln_rope_kernel(
    const float* __restrict__ qkv, const float* __restrict__ rope,
    const float* __restrict__ qg, const float* __restrict__ qb,
    const float* __restrict__ kg, const float* __restrict__ kb,
    float* __restrict__ Q, float* __restrict__ Ko, float* __restrict__ V)
{
    const int warp = threadIdx.x >> 5;
    const int lane = threadIdx.x & 31;
    const long task = (long)blockIdx.x * 8 + warp;
    const int h = (int)(task % NH);
    const int s = (int)((task / NH) % S_LEN);
    const int b = (int)(task / ((long)NH * S_LEN));

    const size_t base = ((size_t)b * S_LEN + s) * QKV_N + h * (3 * HD);
    const int d0 = lane * 2;

    float2 qv = *(const float2*)&qkv[base + d0];
    float2 kv = *(const float2*)&qkv[base + HD + d0];
    float2 vv = *(const float2*)&qkv[base + 2 * HD + d0];

    float2 qn = ln_pair(qv.x, qv.y, qg, qb, d0);
    float2 kn = ln_pair(kv.x, kv.y, kg, kb, d0);

    float4 rr = *(const float4*)&rope[(size_t)s * 128 + lane * 4];
    float q0 = rr.x * qn.x + rr.y * qn.y;
    float q1 = rr.z * qn.x + rr.w * qn.y;
    float k0 = rr.x * kn.x + rr.y * kn.y;
    float k1 = rr.z * kn.x + rr.w * kn.y;

    const size_t ob = (((size_t)b * NH + h) * S_LEN + s) * HD + d0;
    *(float2*)&Q[ob]  = make_float2(q0 * 0.125f, q1 * 0.125f);
    *(float2*)&Ko[ob] = make_float2(k0, k1);
    *(float2*)&V[ob]  = vv;
}

// ============================================================================
// Flash attention, fp32. Epilogue writes bf16 hi/lo planes directly
// (consumed by the out-projection GEMM) -- fp32 intermediate eliminated.
// ============================================================================
#define AST 68
#define ATT_SMEM (4 * 64 * AST * 4)

__global__ void __launch_bounds__(256) attn_kernel(
    const float* __restrict__ Qg, const float* __restrict__ Kg,
    const float* __restrict__ Vg,
    __nv_bfloat16* __restrict__ Oh, __nv_bfloat16* __restrict__ Ol)
{
    extern __shared__ float asm_[];
    float* Qs = asm_;
    float* Ks = asm_ + 64 * AST;
    float* Vs = asm_ + 2 * 64 * AST;
    float* Ps = asm_ + 3 * 64 * AST;

    const int tx = threadIdx.x, ty = threadIdx.y;
    const int tid = ty * 16 + tx;
    const int bh = blockIdx.y;
    const int q0 = blockIdx.x * 64;
    const size_t qbase = ((size_t)bh * S_LEN + q0) * HD;

    int lr[4], ld[4];
    #pragma unroll
    for (int l = 0; l < 4; l++) {
        int idx = tid + l * 256;
        lr[l] = idx >> 4;
        ld[l] = (idx & 15) << 2;
    }

    #pragma unroll
    for (int l = 0; l < 4; l++) {
        float4 v = *(const float4*)&Qg[qbase + (size_t)lr[l] * HD + ld[l]];
        Qs[(ld[l] + 0) * AST + lr[l]] = v.x;
        Qs[(ld[l] + 1) * AST + lr[l]] = v.y;
        Qs[(ld[l] + 2) * AST + lr[l]] = v.z;
        Qs[(ld[l] + 3) * AST + lr[l]] = v.w;
    }

    float m_[4], l_[4], o_[4][4];
    #pragma unroll
    for (int i = 0; i < 4; i++) {
        m_[i] = -FLT_MAX; l_[i] = 0.f;
        #pragma unroll
        for (int j = 0; j < 4; j++) o_[i][j] = 0.f;
    }

    for (int jt = 0; jt < S_LEN / 64; jt++) {
        const size_t kb = ((size_t)bh * S_LEN + jt * 64) * HD;
        float4 kreg[4], vreg[4];
        #pragma unroll
        for (int l = 0; l < 4; l++) {
            kreg[l] = *(const float4*)&Kg[kb + (size_t)lr[l] * HD + ld[l]];
            vreg[l] = *(const float4*)&Vg[kb + (size_t)lr[l] * HD + ld[l]];
        }

        __syncthreads();
        #pragma unroll
        for (int l = 0; l < 4; l++) {
            Ks[(ld[l] + 0) * AST + lr[l]] = kreg[l].x;
            Ks[(ld[l] + 1) * AST + lr[l]] = kreg[l].y;
            Ks[(ld[l] + 2) * AST + lr[l]] = kreg[l].z;
            Ks[(ld[l] + 3) * AST + lr[l]] = kreg[l].w;
            *(float4*)&Vs[lr[l] * AST + ld[l]] = vreg[l];
        }
        __syncthreads();

        float sreg[4][4];
        #pragma unroll
        for (int i = 0; i < 4; i++)
            #pragma unroll
            for (int j = 0; j < 4; j++) sreg[i][j] = 0.f;

        #pragma unroll 8
        for (int d = 0; d < 64; d++) {
            float qa[4], ka[4];
            *(float4*)qa = *(const float4*)&Qs[d * AST + ty * 4];
            *(float4*)ka = *(const float4*)&Ks[d * AST + tx * 4];
            #pragma unroll
            for (int i = 0; i < 4; i++)
                #pragma unroll
                for (int j = 0; j < 4; j++)
                    sreg[i][j] += qa[i] * ka[j];
        }

        #pragma unroll
        for (int i = 0; i < 4; i++) {
            float mx = fmaxf(fmaxf(sreg[i][0], sreg[i][1]),
                             fmaxf(sreg[i][2], sreg[i][3]));
            #pragma unroll
            for (int off = 8; off; off >>= 1)
                mx = fmaxf(mx, __shfl_xor_sync(0xffffffffu, mx, off));
            float mn = fmaxf(m_[i], mx);
            float alpha = __expf(m_[i] - mn);
            m_[i] = mn;
            float rs = 0.f;
            #pragma unroll
            for (int j = 0; j < 4; j++) {
                float p = __expf(sreg[i][j] - mn);
                sreg[i][j] = p;
                rs += p;
            }
            #pragma unroll
            for (int off = 8; off; off >>= 1)
                rs += __shfl_xor_sync(0xffffffffu, rs, off);
            l_[i] = l_[i] * alpha + rs;
            #pragma unroll
            for (int j = 0; j < 4; j++) o_[i][j] *= alpha;
        }

        #pragma unroll
        for (int j = 0; j < 4; j++)
            #pragma unroll
            for (int i = 0; i < 4; i++)
                Ps[(tx * 4 + j) * AST + ty * 4 + i] = sreg[i][j];
        __syncthreads();

        #pragma unroll 8
        for (int c = 0; c < 64; c++) {
            float pa[4], va[4];
            *(float4*)pa = *(const float4*)&Ps[c * AST + ty * 4];
            *(float4*)va = *(const float4*)&Vs[c * AST + tx * 4];
            #pragma unroll
            for (int i = 0; i < 4; i++)
                #pragma unroll
                for (int j = 0; j < 4; j++)
                    o_[i][j] += pa[i] * va[j];
        }
    }

    // epilogue: normalize, split to bf16 hi/lo, scatter to [B, S, C]
    const int b = bh >> 5;
    const int h = bh & 31;
    #pragma unroll
    for (int i = 0; i < 4; i++) {
        float inv = 1.f / l_[i];
        int row = q0 + ty * 4 + i;
        size_t base = ((size_t)b * S_LEN + row) * C_DIM + h * HD + tx * 4;
        __nv_bfloat16 hh[4], ll[4];
        #pragma unroll
        for (int j = 0; j < 4; j++) {
            float v = o_[i][j] * inv;
            hh[j] = __float2bfloat16(v);
            ll[j] = __float2bfloat16(v - __bfloat162float(hh[j]));
        }
        *(uint2*)&Oh[base] = *(const uint2*)hh;
        *(uint2*)&Ol[base] = *(const uint2*)ll;
    }
}

// ============================================================================
// launch
// ============================================================================
extern "C" void kernel_launch(void* const* d_in, const int* in_sizes, int n_in,
                              void* d_out, int out_size)
{
    const float* x    = (const float*)d_in[0];
    const float* rope = (const float*)d_in[1];
    const float* wqkv = (const float*)d_in[2];
    const float* wout = (const float*)d_in[3];
    const float* qg   = (const float*)d_in[4];
    const float* qb   = (const float*)d_in[5];
    const float* kg   = (const float*)d_in[6];
    const float* kb   = (const float*)d_in[7];
    float* out = (float*)d_out;

    float *qkv, *Q, *K, *V;
    __nv_bfloat16 *xh, *xl, *wqh, *wql, *woh, *wol, *ah, *al;
    cudaGetSymbolAddress((void**)&qkv, g_qkv);
    cudaGetSymbolAddress((void**)&Q,   g_q);
    cudaGetSymbolAddress((void**)&K,   g_k);
    cudaGetSymbolAddress((void**)&V,   g_v);
    cudaGetSymbolAddress((void**)&xh,  g_xh);
    cudaGetSymbolAddress((void**)&xl,  g_xl);
    cudaGetSymbolAddress((void**)&wqh, g_wqh);
    cudaGetSymbolAddress((void**)&wql, g_wql);
    cudaGetSymbolAddress((void**)&woh, g_woh);
    cudaGetSymbolAddress((void**)&wol, g_wol);
    cudaGetSymbolAddress((void**)&ah,  g_ah);
    cudaGetSymbolAddress((void**)&al,  g_al);

    cudaFuncSetAttribute(attn_kernel,
                         cudaFuncAttributeMaxDynamicSharedMemorySize, ATT_SMEM);
    cudaFuncSetAttribute(gemm_mma,
                         cudaFuncAttributeMaxDynamicSharedMemorySize, GEMM_SMEM);

    // 0) fp32 -> bf16 hi/lo splits (x, w_qkv, w_out)
    cvt_hilo<<<(M_TOT * C_DIM) / (256 * 8), 256>>>(x,    xh,  xl);
    cvt_hilo<<<(QKV_N * C_DIM) / (256 * 8), 256>>>(wqkv, wqh, wql);
    cvt_hilo<<<(C_DIM * C_DIM) / (256 * 8), 256>>>(wout, woh, wol);

    // 1) QKV projection (HMMA): [4096,2048] x [6144,2048]^T -> [4096,6144]
    gemm_mma<<<dim3(QKV_N / TBN, M_TOT / TBM), 256, GEMM_SMEM>>>(
        xh, xl, wqh, wql, qkv, M_TOT, QKV_N, C_DIM);

    // 2) LN + rope + transpose to [B,H,S,hd]
    ln_rope_kernel<<<(B_DIM * S_LEN * NH) / 8, 256>>>(qkv, rope,
                                                      qg, qb, kg, kb, Q, K, V);
    // 3) flash attention -> bf16 hi/lo planes [B,S,C] (fused cvt)
    attn_kernel<<<dim3(S_LEN / 64, B_DIM * NH), dim3(16, 16), ATT_SMEM>>>(
        Q, K, V, ah, al);

    // 4) out projection (HMMA): [4096,2048] x [2048,2048]^T -> d_out
    gemm_mma<<<dim3(C_DIM / TBN, M_TOT / TBM), 256, GEMM_SMEM>>>(
        ah, al, woh, wol, out, M_TOT, C_DIM, C_DIM);
}